// round 4
// baseline (speedup 1.0000x reference)
#include <cuda_runtime.h>
#include <math.h>
#include <stdint.h>

// Problem shapes (fixed by the dataset)
#define BB 8
#define SS 2048
#define DD 512
#define HH 1024
#define CC 16

// Scratch (device globals: allocation-free per harness rules)
__device__ float g_r[BB * SS * HH];           // 64 MB  : r = x W1^T + b1
__device__ float g_rT[BB * SS * HH];          // 64 MB  : r transposed [b][h][s]
__device__ float g_s[(size_t)BB * SS * SS];   // 128 MB : scores / attn
__device__ float g_att[BB * SS * HH];         // 64 MB  : attended

__device__ __forceinline__ uint32_t f2tf32(float x) {
    uint32_t y;
    asm("cvt.rna.tf32.f32 %0, %1;" : "=r"(y) : "f"(x));
    return y;
}

__device__ __forceinline__ void mma_tf32(float* c, const uint32_t* a, const uint32_t* b) {
    asm volatile(
        "mma.sync.aligned.m16n8k8.row.col.f32.tf32.tf32.f32 "
        "{%0,%1,%2,%3}, {%4,%5,%6,%7}, {%8,%9}, {%0,%1,%2,%3};\n"
        : "+f"(c[0]), "+f"(c[1]), "+f"(c[2]), "+f"(c[3])
        : "r"(a[0]), "r"(a[1]), "r"(a[2]), "r"(a[3]), "r"(b[0]), "r"(b[1]));
}

__device__ __forceinline__ void ldsm_x4(uint32_t& r0, uint32_t& r1, uint32_t& r2,
                                        uint32_t& r3, uint32_t addr) {
    asm volatile("ldmatrix.sync.aligned.m8n8.x4.shared.b16 {%0,%1,%2,%3}, [%4];"
                 : "=r"(r0), "=r"(r1), "=r"(r2), "=r"(r3) : "r"(addr));
}

// ---------------------------------------------------------------------------
// TF32 tensor-core NT GEMM: C[m,n] = sum_k A[m,k]*B[n,k]  (+bias[n])
// A row-major [M,K], B row-major [N,K] (both k-contiguous).
// Block tile 128x256x16, 8 warps (2m x 4n), warp tile 64x64 (4x8 m16n8k8).
// Smem rows [m][16k] padded to 20 words: 20*m mod 32 covers all bank quads ->
// conflict-free STS.128 stores AND conflict-free ldmatrix phases.
// Double-buffered, one __syncthreads per k16 tile.
// ---------------------------------------------------------------------------
#define PAD 20
#define A_WORDS (128 * PAD)
#define B_WORDS (256 * PAD)
#define SMEM_BYTES ((2 * A_WORDS + 2 * B_WORDS) * 4)

__global__ __launch_bounds__(256, 1) void mma_gemm_nt(
    const float* __restrict__ A, const float* __restrict__ B,
    float* __restrict__ C, int M, int N, int K,
    size_t sA, size_t sB, size_t sC, const float* __restrict__ bias)
{
    extern __shared__ __align__(16) uint32_t dynsmem[];
    uint32_t* As = dynsmem;                 // [2][128][PAD]
    uint32_t* Bs = dynsmem + 2 * A_WORDS;   // [2][256][PAD]

    const int tid = threadIdx.x;
    const int warp = tid >> 5, lane = tid & 31;
    const int g  = lane >> 2;           // groupID (0..7)
    const int tg = lane & 3;            // thread-in-group (0..3)
    const int wm = (warp & 1) * 64;     // warp m offset
    const int wn = (warp >> 1) * 64;    // warp n offset

    A += (size_t)blockIdx.z * sA + (size_t)blockIdx.y * 128 * K;
    B += (size_t)blockIdx.z * sB + (size_t)blockIdx.x * 256 * K;
    C += (size_t)blockIdx.z * sC + (size_t)blockIdx.y * 128 * N + (size_t)blockIdx.x * 256;

    // loader: lane L handles row w*8 + (L&7) (+64p), k-chunk (L>>3)*4
    const int lrow = warp * 8 + (lane & 7);
    const int lkc  = (lane >> 3) * 4;

    const uint32_t smem_base = (uint32_t)__cvta_generic_to_shared(dynsmem);
    const uint32_t As_b0 = smem_base;
    const uint32_t Bs_b0 = smem_base + 2 * A_WORDS * 4;

    float4 ra[2], rb[4];

    float acc[4][8][4];
#pragma unroll
    for (int i = 0; i < 4; i++)
#pragma unroll
        for (int j = 0; j < 8; j++)
#pragma unroll
            for (int q = 0; q < 4; q++) acc[i][j][q] = 0.f;

#define LOADG(kt)                                                               \
    {                                                                           \
        _Pragma("unroll")                                                       \
        for (int p = 0; p < 2; p++)                                             \
            ra[p] = *(const float4*)(A + (size_t)(lrow + 64 * p) * K + (kt) + lkc); \
        _Pragma("unroll")                                                       \
        for (int p = 0; p < 4; p++)                                             \
            rb[p] = *(const float4*)(B + (size_t)(lrow + 64 * p) * K + (kt) + lkc); \
    }

#define STORES(bi)                                                              \
    {                                                                           \
        _Pragma("unroll")                                                       \
        for (int p = 0; p < 2; p++) {                                           \
            uint4 w = make_uint4(f2tf32(ra[p].x), f2tf32(ra[p].y),              \
                                 f2tf32(ra[p].z), f2tf32(ra[p].w));             \
            *(uint4*)&As[(bi) * A_WORDS + (lrow + 64 * p) * PAD + lkc] = w;     \
        }                                                                       \
        _Pragma("unroll")                                                       \
        for (int p = 0; p < 4; p++) {                                           \
            uint4 w = make_uint4(f2tf32(rb[p].x), f2tf32(rb[p].y),              \
                                 f2tf32(rb[p].z), f2tf32(rb[p].w));             \
            *(uint4*)&Bs[(bi) * B_WORDS + (lrow + 64 * p) * PAD + lkc] = w;     \
        }                                                                       \
    }

#define COMPUTE(bi)                                                             \
    {                                                                           \
        const int idx = lane >> 3, lr8 = lane & 7;                              \
        _Pragma("unroll")                                                       \
        for (int kk = 0; kk < 16; kk += 8) {                                    \
            uint32_t afr[4][4], bfr[8][2];                                      \
            _Pragma("unroll")                                                   \
            for (int mt = 0; mt < 4; mt++) {                                    \
                int row = wm + mt * 16 + lr8 + (idx & 1) * 8;                   \
                int kof = kk + (idx >> 1) * 4;                                  \
                uint32_t ad = As_b0 + ((bi) * A_WORDS + row * PAD + kof) * 4;   \
                ldsm_x4(afr[mt][0], afr[mt][1], afr[mt][2], afr[mt][3], ad);    \
            }                                                                   \
            _Pragma("unroll")                                                   \
            for (int pt = 0; pt < 4; pt++) {                                    \
                int row = wn + pt * 16 + lr8 + (idx >> 1) * 8;                  \
                int kof = kk + (idx & 1) * 4;                                   \
                uint32_t bd = Bs_b0 + ((bi) * B_WORDS + row * PAD + kof) * 4;   \
                ldsm_x4(bfr[2 * pt][0], bfr[2 * pt][1],                         \
                        bfr[2 * pt + 1][0], bfr[2 * pt + 1][1], bd);            \
            }                                                                   \
            _Pragma("unroll")                                                   \
            for (int mt = 0; mt < 4; mt++)                                      \
                _Pragma("unroll")                                               \
                for (int nt = 0; nt < 8; nt++)                                  \
                    mma_tf32(acc[mt][nt], afr[mt], bfr[nt]);                    \
        }                                                                       \
    }

    const int ktiles = K / 16;
    LOADG(0);
    STORES(0);
    __syncthreads();
    int buf = 0;
    for (int kt = 1; kt < ktiles; kt++) {
        LOADG(kt * 16);
        COMPUTE(buf);
        STORES(buf ^ 1);
        __syncthreads();
        buf ^= 1;
    }
    COMPUTE(buf);

    // epilogue: c0,c1 at (g, 2tg), c2,c3 at (g+8, 2tg) within each m16n8 tile
#pragma unroll
    for (int mt = 0; mt < 4; mt++) {
#pragma unroll
        for (int nt = 0; nt < 8; nt++) {
            int n0 = wn + nt * 8 + 2 * tg;
            int m0 = wm + mt * 16 + g;
            float2 v0 = make_float2(acc[mt][nt][0], acc[mt][nt][1]);
            float2 v1 = make_float2(acc[mt][nt][2], acc[mt][nt][3]);
            if (bias) {
                float bx0 = bias[blockIdx.x * 256 + n0];
                float bx1 = bias[blockIdx.x * 256 + n0 + 1];
                v0.x += bx0; v0.y += bx1;
                v1.x += bx0; v1.y += bx1;
            }
            *(float2*)(C + (size_t)m0 * N + n0) = v0;
            *(float2*)(C + (size_t)(m0 + 8) * N + n0) = v1;
        }
    }
#undef LOADG
#undef STORES
#undef COMPUTE
}

// ---------------------------------------------------------------------------
// Transpose r[b][s][h] -> rT[b][h][s]  (32x32 tiles, 256 threads)
// ---------------------------------------------------------------------------
__global__ __launch_bounds__(256) void transpose_k(const float* __restrict__ in,
                                                   float* __restrict__ out)
{
    __shared__ float t[32][33];
    const int b = blockIdx.z;
    const int s0 = blockIdx.x * 32, h0 = blockIdx.y * 32;
    const float* ip = in + (size_t)b * SS * HH;
    float* op = out + (size_t)b * HH * SS;
    const int tx = threadIdx.x & 31, ty = threadIdx.x >> 5;
#pragma unroll
    for (int i = 0; i < 32; i += 8)
        t[ty + i][tx] = ip[(size_t)(s0 + ty + i) * HH + h0 + tx];
    __syncthreads();
#pragma unroll
    for (int i = 0; i < 32; i += 8)
        op[(size_t)(h0 + ty + i) * SS + s0 + tx] = t[tx][ty + i];
}

// ---------------------------------------------------------------------------
// Row softmax with max subtraction. One block (256 threads) per row of n.
// ---------------------------------------------------------------------------
__global__ __launch_bounds__(256) void softmax_rows(float* __restrict__ s, int n)
{
    float* row = s + (size_t)blockIdx.x * n;
    const int tid = threadIdx.x;
    const int lane = tid & 31, warp = tid >> 5;
    __shared__ float red[8];

    float m = -INFINITY;
    for (int j = tid; j < n; j += 256) m = fmaxf(m, row[j]);
#pragma unroll
    for (int o = 16; o; o >>= 1) m = fmaxf(m, __shfl_xor_sync(0xFFFFFFFFu, m, o));
    if (lane == 0) red[warp] = m;
    __syncthreads();
    m = red[0];
#pragma unroll
    for (int w = 1; w < 8; w++) m = fmaxf(m, red[w]);
    __syncthreads();

    float sum = 0.f;
    for (int j = tid; j < n; j += 256) {
        float e = __expf(row[j] - m);
        row[j] = e;
        sum += e;
    }
#pragma unroll
    for (int o = 16; o; o >>= 1) sum += __shfl_xor_sync(0xFFFFFFFFu, sum, o);
    if (lane == 0) red[warp] = sum;
    __syncthreads();
    sum = 0.f;
#pragma unroll
    for (int w = 0; w < 8; w++) sum += red[w];
    float inv = 1.f / sum;
    for (int j = tid; j < n; j += 256) row[j] *= inv;
}

// ---------------------------------------------------------------------------
// Fused: t = attended + r ; y = LN(t)*gamma+beta ; out = y W2^T + b2
// One block (256 threads) per row (16384 rows). C=16 classes.
// ---------------------------------------------------------------------------
__global__ __launch_bounds__(256) void ln_proj_kernel(
    const float* __restrict__ att, const float* __restrict__ r,
    const float* __restrict__ gamma, const float* __restrict__ beta,
    const float* __restrict__ W2, const float* __restrict__ b2,
    float* __restrict__ out)
{
    __shared__ float t[HH];
    __shared__ float red[16];
    __shared__ float part[CC * 8];

    const size_t m = blockIdx.x;
    const float* ar = att + m * HH;
    const float* rr = r + m * HH;
    const int tid = threadIdx.x;
    const int lane = tid & 31, warp = tid >> 5;

    float s = 0.f, s2 = 0.f;
    for (int h = tid; h < HH; h += 256) {
        float v = ar[h] + rr[h];
        t[h] = v;
        s += v;
        s2 += v * v;
    }
#pragma unroll
    for (int o = 16; o; o >>= 1) {
        s  += __shfl_xor_sync(0xFFFFFFFFu, s, o);
        s2 += __shfl_xor_sync(0xFFFFFFFFu, s2, o);
    }
    if (lane == 0) { red[warp] = s; red[8 + warp] = s2; }
    __syncthreads();
    s = 0.f; s2 = 0.f;
#pragma unroll
    for (int w = 0; w < 8; w++) { s += red[w]; s2 += red[8 + w]; }
    const float mu = s * (1.f / HH);
    const float var = s2 * (1.f / HH) - mu * mu;
    const float rstd = rsqrtf(var + 1e-5f);

    float acc[CC] = {};
    for (int h = tid; h < HH; h += 256) {
        float yv = (t[h] - mu) * rstd * gamma[h] + beta[h];
#pragma unroll
        for (int c = 0; c < CC; c++)
            acc[c] = fmaf(yv, W2[c * HH + h], acc[c]);
    }
#pragma unroll
    for (int c = 0; c < CC; c++) {
#pragma unroll
        for (int o = 16; o; o >>= 1)
            acc[c] += __shfl_xor_sync(0xFFFFFFFFu, acc[c], o);
    }
    if (lane == 0) {
#pragma unroll
        for (int c = 0; c < CC; c++) part[c * 8 + warp] = acc[c];
    }
    __syncthreads();
    if (tid < CC) {
        float v = 0.f;
#pragma unroll
        for (int w = 0; w < 8; w++) v += part[tid * 8 + w];
        out[m * CC + tid] = v + b2[tid];
    }
}

// ---------------------------------------------------------------------------
// One-time init on the first (uncaptured) correctness call: symbol addresses
// + dynamic-smem opt-in for the GEMM.
// ---------------------------------------------------------------------------
struct Scratch {
    float *r, *rT, *s, *att;
    Scratch() {
        cudaGetSymbolAddress((void**)&r,   g_r);
        cudaGetSymbolAddress((void**)&rT,  g_rT);
        cudaGetSymbolAddress((void**)&s,   g_s);
        cudaGetSymbolAddress((void**)&att, g_att);
        cudaFuncSetAttribute(mma_gemm_nt,
                             cudaFuncAttributeMaxDynamicSharedMemorySize,
                             SMEM_BYTES);
    }
};

extern "C" void kernel_launch(void* const* d_in, const int* in_sizes, int n_in,
                              void* d_out, int out_size)
{
    const float* x     = (const float*)d_in[0];
    const float* W1    = (const float*)d_in[1];
    const float* b1    = (const float*)d_in[2];
    const float* gamma = (const float*)d_in[3];
    const float* beta  = (const float*)d_in[4];
    const float* W2    = (const float*)d_in[5];
    const float* b2    = (const float*)d_in[6];
    float* out = (float*)d_out;

    static Scratch sc;
    float* r_p   = sc.r;
    float* rT_p  = sc.rT;
    float* s_p   = sc.s;
    float* att_p = sc.att;

    // 1) r = x W1^T + b1     [16384,512] x [1024,512]^T -> [16384,1024]
    {
        dim3 grid(HH / 256, (BB * SS) / 128, 1);
        mma_gemm_nt<<<grid, 256, SMEM_BYTES>>>(x, W1, r_p, BB * SS, HH, DD,
                                               0, 0, 0, b1);
    }
    // 1b) rT = transpose(r) per batch
    {
        dim3 grid(SS / 32, HH / 32, BB);
        transpose_k<<<grid, 256>>>(r_p, rT_p);
    }
    // 2) scores = r r^T per batch   [2048,1024] x [2048,1024]^T -> [2048,2048]
    {
        dim3 grid(SS / 256, SS / 128, BB);
        mma_gemm_nt<<<grid, 256, SMEM_BYTES>>>(r_p, r_p, s_p, SS, SS, HH,
                                               (size_t)SS * HH, (size_t)SS * HH,
                                               (size_t)SS * SS, nullptr);
    }
    // 3) softmax rows
    softmax_rows<<<BB * SS, 256>>>(s_p, SS);

    // 4) attended = P r per batch : NT with rT  [2048,2048] x [1024,2048]^T
    {
        dim3 grid(HH / 256, SS / 128, BB);
        mma_gemm_nt<<<grid, 256, SMEM_BYTES>>>(s_p, rT_p, att_p, SS, HH, SS,
                                               (size_t)SS * SS, (size_t)SS * HH,
                                               (size_t)SS * HH, nullptr);
    }
    // 5) fused residual + LayerNorm + classifier
    ln_proj_kernel<<<BB * SS, 256>>>(att_p, r_p, gamma, beta, W2, b2, out);
}